// round 1
// baseline (speedup 1.0000x reference)
#include <cuda_runtime.h>

// EMA along T with geometric-decay chunking.
// x: [B=8, T=4096, F=1024] fp32, y_t = a*y_{t-1} + (1-a)*x_t, y_{-1}=0.
// alpha=0.9 -> alpha^192 ~ 1.7e-9, so each chunk of 256 timesteps can
// reconstruct its carry-in from a 192-step lookback started at y=0.
// All chunks are then independent -> one fully parallel kernel.

#define T_DIM    4096
#define F_DIM    1024
#define B_DIM    8
#define CHUNK    256
#define LOOKBACK 192
#define ALPHA    0.9f
#define OMALPHA  0.1f

#define F4 (F_DIM / 4)   // 256 float4 lanes across features

__global__ __launch_bounds__(128, 2)
void ema_chunk_kernel(const float* __restrict__ x, float* __restrict__ y) {
    // feature (float4 granularity): 2 blocks in x cover 256 float4 lanes
    const int f4 = blockIdx.x * blockDim.x + threadIdx.x;   // 0..255
    const int chunk = blockIdx.y;                            // 0..15
    const int b = blockIdx.z;                                // 0..7

    const int t0 = chunk * CHUNK;
    const int tw = (t0 >= LOOKBACK) ? (t0 - LOOKBACK) : 0;   // warmup start

    // base pointers at (b, 0, f4) in float4 units; row stride = F4 float4s
    const float4* __restrict__ xp =
        reinterpret_cast<const float4*>(x) + (size_t)b * T_DIM * F4 + f4;
    float4* __restrict__ yp =
        reinterpret_cast<float4*>(y) + (size_t)b * T_DIM * F4 + f4;

    float ax = 0.f, ay = 0.f, az = 0.f, aw = 0.f;

    // ---- warmup: reconstruct carry over [tw, t0) ----
    int t = tw;
    #pragma unroll 8
    for (; t < t0; ++t) {
        float4 v = __ldg(&xp[(size_t)t * F4]);
        ax = fmaf(ALPHA, ax, OMALPHA * v.x);
        ay = fmaf(ALPHA, ay, OMALPHA * v.y);
        az = fmaf(ALPHA, az, OMALPHA * v.z);
        aw = fmaf(ALPHA, aw, OMALPHA * v.w);
    }

    // ---- main: produce outputs for [t0, t0+CHUNK) ----
    #pragma unroll 8
    for (int i = 0; i < CHUNK; ++i) {
        const int tt = t0 + i;
        float4 v = __ldg(&xp[(size_t)tt * F4]);
        ax = fmaf(ALPHA, ax, OMALPHA * v.x);
        ay = fmaf(ALPHA, ay, OMALPHA * v.y);
        az = fmaf(ALPHA, az, OMALPHA * v.z);
        aw = fmaf(ALPHA, aw, OMALPHA * v.w);
        float4 o; o.x = ax; o.y = ay; o.z = az; o.w = aw;
        yp[(size_t)tt * F4] = o;
    }
}

extern "C" void kernel_launch(void* const* d_in, const int* in_sizes, int n_in,
                              void* d_out, int out_size) {
    (void)in_sizes; (void)n_in; (void)out_size;
    const float* x = (const float*)d_in[0];
    float* y = (float*)d_out;

    dim3 block(128, 1, 1);
    dim3 grid(F4 / 128, T_DIM / CHUNK, B_DIM);   // (2, 16, 8) = 256 blocks
    ema_chunk_kernel<<<grid, block>>>(x, y);
}

// round 2
// speedup vs baseline: 1.1049x; 1.1049x over previous
#include <cuda_runtime.h>

// EMA along T with geometric-decay chunking, round 2.
// x: [B=8, T=4096, F=1024] fp32, y_t = 0.9*y_{t-1} + 0.1*x_t, y_{-1}=0.
// 0.9^128 ~ 1.4e-6 << 1e-3 threshold -> each 128-step chunk reconstructs its
// carry from a 128-step lookback. All chunks independent -> one parallel kernel.
//
// R2 changes vs R1 (72.4us, DRAM 60.9%, occ 10.3%):
//  - CHUNK 256->128, LOOKBACK 192->128: 512 blocks / 2048 warps, single
//    balanced wave (~14 warps/SM) instead of unbalanced 1.73 waves.
//  - chunk index moved to gridDim.x: adjacent chunks -> adjacent SMs ->
//    lookback reads hit L2 lines their neighbor just streamed.
//  - y written with st.global.cs (streaming): y is never re-read; don't let
//    it evict x from L2.

#define T_DIM    4096
#define F_DIM    1024
#define B_DIM    8
#define CHUNK    128
#define LOOKBACK 128
#define ALPHA    0.9f
#define OMALPHA  0.1f

#define F4 (F_DIM / 4)        // 256 float4 lanes across features
#define NCHUNK (T_DIM / CHUNK) // 32

__device__ __forceinline__ void stcs4(float4* p, float4 v) {
    asm volatile("st.global.cs.v4.f32 [%0], {%1,%2,%3,%4};"
                 :: "l"(p), "f"(v.x), "f"(v.y), "f"(v.z), "f"(v.w) : "memory");
}

__global__ __launch_bounds__(128, 4)
void ema_chunk_kernel(const float* __restrict__ x, float* __restrict__ y) {
    const int chunk = blockIdx.x;                             // 0..31 (fastest -> adjacent SMs)
    const int f4 = blockIdx.y * blockDim.x + threadIdx.x;     // 0..255
    const int b = blockIdx.z;                                 // 0..7

    const int t0 = chunk * CHUNK;
    const int tw = (t0 >= LOOKBACK) ? (t0 - LOOKBACK) : 0;

    const float4* __restrict__ xp =
        reinterpret_cast<const float4*>(x) + (size_t)b * T_DIM * F4 + f4;
    float4* __restrict__ yp =
        reinterpret_cast<float4*>(y) + (size_t)b * T_DIM * F4 + f4;

    float ax = 0.f, ay = 0.f, az = 0.f, aw = 0.f;

    // ---- warmup: reconstruct carry over [tw, t0) ----
    #pragma unroll 8
    for (int t = tw; t < t0; ++t) {
        float4 v = __ldg(&xp[(size_t)t * F4]);
        ax = fmaf(ALPHA, ax, OMALPHA * v.x);
        ay = fmaf(ALPHA, ay, OMALPHA * v.y);
        az = fmaf(ALPHA, az, OMALPHA * v.z);
        aw = fmaf(ALPHA, aw, OMALPHA * v.w);
    }

    // ---- main: produce outputs for [t0, t0+CHUNK) ----
    #pragma unroll 8
    for (int i = 0; i < CHUNK; ++i) {
        const int tt = t0 + i;
        float4 v = __ldg(&xp[(size_t)tt * F4]);
        ax = fmaf(ALPHA, ax, OMALPHA * v.x);
        ay = fmaf(ALPHA, ay, OMALPHA * v.y);
        az = fmaf(ALPHA, az, OMALPHA * v.z);
        aw = fmaf(ALPHA, aw, OMALPHA * v.w);
        float4 o; o.x = ax; o.y = ay; o.z = az; o.w = aw;
        stcs4(&yp[(size_t)tt * F4], o);
    }
}

extern "C" void kernel_launch(void* const* d_in, const int* in_sizes, int n_in,
                              void* d_out, int out_size) {
    (void)in_sizes; (void)n_in; (void)out_size;
    const float* x = (const float*)d_in[0];
    float* y = (float*)d_out;

    dim3 block(128, 1, 1);
    dim3 grid(NCHUNK, F4 / 128, B_DIM);   // (32, 2, 8) = 512 blocks
    ema_chunk_kernel<<<grid, block>>>(x, y);
}

// round 3
// speedup vs baseline: 1.1320x; 1.0245x over previous
#include <cuda_runtime.h>

// EMA along T with geometric-decay chunking, round 3.
// x: [B=8, T=4096, F=1024] fp32, y_t = 0.9*y_{t-1} + 0.1*x_t, y_{-1}=0.
// 0.9^128 ~ 1.4e-6 << 1e-3 threshold -> each 128-step chunk reconstructs its
// carry from a 128-step lookback started at 0. All chunks independent.
//
// R3 changes vs R2 (65.6us, DRAM 76.8%, occ 19.8%, issue 9.4%):
//  - float4 -> float2 feature lanes: 512 lanes -> 1024 blocks / 4096 warps
//    (~27 warps/SM), doubling chip-wide memory-level parallelism. R2 was
//    concurrency-limited (DRAM 76.8%), not BW-saturated.
//  - __launch_bounds__(128, 8) so ~7 blocks/SM co-reside in one wave.
//  - keep: chunk-major blockIdx.x (neighbor-chunk L2 reuse of lookback),
//    st.global.cs streaming stores for y.

#define T_DIM    4096
#define F_DIM    1024
#define B_DIM    8
#define CHUNK    128
#define LOOKBACK 128
#define ALPHA    0.9f
#define OMALPHA  0.1f

#define F2 (F_DIM / 2)          // 512 float2 lanes across features
#define NCHUNK (T_DIM / CHUNK)  // 32

__device__ __forceinline__ void stcs2(float2* p, float2 v) {
    asm volatile("st.global.cs.v2.f32 [%0], {%1,%2};"
                 :: "l"(p), "f"(v.x), "f"(v.y) : "memory");
}

__global__ __launch_bounds__(128, 8)
void ema_chunk_kernel(const float* __restrict__ x, float* __restrict__ y) {
    const int chunk = blockIdx.x;                             // 0..31 (fastest -> adjacent SMs)
    const int f2 = blockIdx.y * blockDim.x + threadIdx.x;     // 0..511
    const int b = blockIdx.z;                                 // 0..7

    const int t0 = chunk * CHUNK;
    const int tw = (t0 >= LOOKBACK) ? (t0 - LOOKBACK) : 0;

    const float2* __restrict__ xp =
        reinterpret_cast<const float2*>(x) + (size_t)b * T_DIM * F2 + f2;
    float2* __restrict__ yp =
        reinterpret_cast<float2*>(y) + (size_t)b * T_DIM * F2 + f2;

    float ax = 0.f, ay = 0.f;

    // ---- warmup: reconstruct carry over [tw, t0) ----
    #pragma unroll 16
    for (int t = tw; t < t0; ++t) {
        float2 v = __ldg(&xp[(size_t)t * F2]);
        ax = fmaf(ALPHA, ax, OMALPHA * v.x);
        ay = fmaf(ALPHA, ay, OMALPHA * v.y);
    }

    // ---- main: produce outputs for [t0, t0+CHUNK) ----
    #pragma unroll 16
    for (int i = 0; i < CHUNK; ++i) {
        const int tt = t0 + i;
        float2 v = __ldg(&xp[(size_t)tt * F2]);
        ax = fmaf(ALPHA, ax, OMALPHA * v.x);
        ay = fmaf(ALPHA, ay, OMALPHA * v.y);
        float2 o; o.x = ax; o.y = ay;
        stcs2(&yp[(size_t)tt * F2], o);
    }
}

extern "C" void kernel_launch(void* const* d_in, const int* in_sizes, int n_in,
                              void* d_out, int out_size) {
    (void)in_sizes; (void)n_in; (void)out_size;
    const float* x = (const float*)d_in[0];
    float* y = (float*)d_out;

    dim3 block(128, 1, 1);
    dim3 grid(NCHUNK, F2 / 128, B_DIM);   // (32, 4, 8) = 1024 blocks
    ema_chunk_kernel<<<grid, block>>>(x, y);
}

// round 4
// speedup vs baseline: 1.4578x; 1.2878x over previous
#include <cuda_runtime.h>

// EMA along T with geometric-decay chunking, round 4.
// x: [B=8, T=4096, F=1024] fp32, y_t = 0.9*y_{t-1} + 0.1*x_t, y_{-1}=0.
// Each chunk reconstructs its carry from a LOOKBACK-step warmup started at 0;
// truncation ~ 0.9^(LOOKBACK+1) << 1e-3 gate. All chunks independent.
//
// R4 changes vs R3 (64.0us, DRAM 75.1% @ 340MB traffic, occ 38.9%):
//  R3 showed doubling occupancy bought nothing -> we sit at a ~6TB/s DRAM
//  wall; the lever is BYTES. Read amplification was 1.54x at DRAM.
//  - CHUNK 128->256, LOOKBACK 128->96: L2-level read amp 2.0x -> 1.37x.
//    0.9^97 ~ 3.6e-5, still 27x under the rel-err gate (R3 measured 2.5e-7
//    with 0.9^128~1.4e-6; error model verified).
//  - grid back to 512 blocks (~14 warps/SM) = R2 occupancy, which hit the
//    same DRAM% as R3's 28 warps/SM.
//  - keep: float2 lanes, chunk-major blockIdx.x, st.global.cs for y.

#define T_DIM    4096
#define F_DIM    1024
#define B_DIM    8
#define CHUNK    256
#define LOOKBACK 96
#define ALPHA    0.9f
#define OMALPHA  0.1f

#define F2 (F_DIM / 2)          // 512 float2 lanes across features
#define NCHUNK (T_DIM / CHUNK)  // 16

__device__ __forceinline__ void stcs2(float2* p, float2 v) {
    asm volatile("st.global.cs.v2.f32 [%0], {%1,%2};"
                 :: "l"(p), "f"(v.x), "f"(v.y) : "memory");
}

__global__ __launch_bounds__(128, 8)
void ema_chunk_kernel(const float* __restrict__ x, float* __restrict__ y) {
    const int chunk = blockIdx.x;                             // 0..15 (fastest -> adjacent SMs)
    const int f2 = blockIdx.y * blockDim.x + threadIdx.x;     // 0..511
    const int b = blockIdx.z;                                 // 0..7

    const int t0 = chunk * CHUNK;
    const int tw = (t0 >= LOOKBACK) ? (t0 - LOOKBACK) : 0;

    const float2* __restrict__ xp =
        reinterpret_cast<const float2*>(x) + (size_t)b * T_DIM * F2 + f2;
    float2* __restrict__ yp =
        reinterpret_cast<float2*>(y) + (size_t)b * T_DIM * F2 + f2;

    float ax = 0.f, ay = 0.f;

    // ---- warmup: reconstruct carry over [tw, t0) ----
    #pragma unroll 16
    for (int t = tw; t < t0; ++t) {
        float2 v = __ldg(&xp[(size_t)t * F2]);
        ax = fmaf(ALPHA, ax, OMALPHA * v.x);
        ay = fmaf(ALPHA, ay, OMALPHA * v.y);
    }

    // ---- main: produce outputs for [t0, t0+CHUNK) ----
    #pragma unroll 16
    for (int i = 0; i < CHUNK; ++i) {
        const int tt = t0 + i;
        float2 v = __ldg(&xp[(size_t)tt * F2]);
        ax = fmaf(ALPHA, ax, OMALPHA * v.x);
        ay = fmaf(ALPHA, ay, OMALPHA * v.y);
        float2 o; o.x = ax; o.y = ay;
        stcs2(&yp[(size_t)tt * F2], o);
    }
}

extern "C" void kernel_launch(void* const* d_in, const int* in_sizes, int n_in,
                              void* d_out, int out_size) {
    (void)in_sizes; (void)n_in; (void)out_size;
    const float* x = (const float*)d_in[0];
    float* y = (float*)d_out;

    dim3 block(128, 1, 1);
    dim3 grid(NCHUNK, F2 / 128, B_DIM);   // (16, 4, 8) = 512 blocks
    ema_chunk_kernel<<<grid, block>>>(x, y);
}